// round 16
// baseline (speedup 1.0000x reference)
#include <cuda_runtime.h>
#include <cuda_bf16.h>
#include <cstdint>
#include <math.h>
#include <float.h>

#define SLEN 2048
#define DM   2048
#define NH   16
#define NKV  4
#define DH   128

// ---------------- scratch (__device__ globals; no allocs allowed) ----------
__device__ float2 g_rot[SLEN * 64];

__device__ __nv_bfloat16 g_xqh[SLEN * DM], g_xql[SLEN * DM];
__device__ __nv_bfloat16 g_xkh[SLEN * DM], g_xkl[SLEN * DM];
__device__ __nv_bfloat16 g_xvh[SLEN * DM], g_xvl[SLEN * DM];
__device__ __nv_bfloat16 g_zh [SLEN * DM], g_zl [SLEN * DM];
__device__ __nv_bfloat16 g_wqh[NH  * DH * DM], g_wql[NH  * DH * DM];
__device__ __nv_bfloat16 g_wkh[NKV * DH * DM], g_wkl[NKV * DH * DM];
__device__ __nv_bfloat16 g_wvh[NKV * DH * DM], g_wvl[NKV * DH * DM];
__device__ __nv_bfloat16 g_woh[DM * DM],       g_wol[DM * DM];
__device__ __nv_bfloat16 g_qAh[SLEN * DM],        g_qAl[SLEN * DM];
__device__ __nv_bfloat16 g_kAh[SLEN * NKV * DH],  g_kAl[SLEN * NKV * DH];
__device__ __nv_bfloat16 g_vAh[SLEN * NKV * DH],  g_vAl[SLEN * NKV * DH];

// ---------------- helpers (sm_80-level features only) ----------------------
static __device__ __forceinline__ uint32_t s2u(const void* p) {
    uint32_t a;
    asm("{ .reg .u64 t; cvta.to.shared.u64 t, %1; cvt.u32.u64 %0, t; }"
        : "=r"(a) : "l"(p));
    return a;
}
static __device__ __forceinline__ void cp16(uint32_t dst, const void* src) {
    asm volatile("cp.async.cg.shared.global [%0], [%1], 16;"
                 :: "r"(dst), "l"(src) : "memory");
}
static __device__ __forceinline__ void cp_commit() {
    asm volatile("cp.async.commit_group;" ::: "memory");
}
template <int N>
static __device__ __forceinline__ void cp_wait() {
    asm volatile("cp.async.wait_group %0;" :: "n"(N) : "memory");
}
static __device__ __forceinline__ void ldm_x4(uint32_t& r0, uint32_t& r1,
                                              uint32_t& r2, uint32_t& r3, uint32_t a) {
    asm volatile("ldmatrix.sync.aligned.m8n8.x4.shared.b16 {%0,%1,%2,%3}, [%4];"
                 : "=r"(r0), "=r"(r1), "=r"(r2), "=r"(r3) : "r"(a));
}
static __device__ __forceinline__ void ldm_x4_t(uint32_t& r0, uint32_t& r1,
                                                uint32_t& r2, uint32_t& r3, uint32_t a) {
    asm volatile("ldmatrix.sync.aligned.m8n8.x4.trans.shared.b16 {%0,%1,%2,%3}, [%4];"
                 : "=r"(r0), "=r"(r1), "=r"(r2), "=r"(r3) : "r"(a));
}
static __device__ __forceinline__ void ldm_x2(uint32_t& r0, uint32_t& r1, uint32_t a) {
    asm volatile("ldmatrix.sync.aligned.m8n8.x2.shared.b16 {%0,%1}, [%2];"
                 : "=r"(r0), "=r"(r1) : "r"(a));
}
static __device__ __forceinline__ void mma16816(float* d, const uint32_t* a,
                                                const uint32_t* b) {
    asm volatile(
        "mma.sync.aligned.m16n8k16.row.col.f32.bf16.bf16.f32 "
        "{%0,%1,%2,%3}, {%4,%5,%6,%7}, {%8,%9}, {%0,%1,%2,%3};"
        : "+f"(d[0]), "+f"(d[1]), "+f"(d[2]), "+f"(d[3])
        : "r"(a[0]), "r"(a[1]), "r"(a[2]), "r"(a[3]), "r"(b[0]), "r"(b[1]));
}
static __device__ __forceinline__ uint32_t packbf(float x, float y) {
    __nv_bfloat162 t = __floats2bfloat162_rn(x, y);
    return *(uint32_t*)&t;
}

// ---------------------------------------------------------------------------
// Merged pre-pass (single launch, range-dispatched over 1D grid).
// ---------------------------------------------------------------------------
#define PRE_SPLIT3 12288
#define PRE_QKVW   (PRE_SPLIT3 + 6144)
#define PRE_WO     (PRE_QKVW + 4096)
#define PRE_TOTAL  (PRE_WO + 512)

static __device__ __forceinline__ void transpose_split_body(
    float t[32][33], const float* __restrict__ Wz,
    __nv_bfloat16* __restrict__ Thz, __nv_bfloat16* __restrict__ Tlz,
    int n0, int k0, int ldw, int ldt)
{
    const int tx = threadIdx.x & 31, ty = threadIdx.x >> 5;
#pragma unroll
    for (int r = 0; r < 4; r++)
        t[ty + 8 * r][tx] = Wz[(size_t)(k0 + ty + 8 * r) * ldw + n0 + tx];
    __syncthreads();
#pragma unroll
    for (int r = 0; r < 4; r++) {
        int n = n0 + ty + 8 * r, k = k0 + tx;
        float v = t[tx][ty + 8 * r];
        __nv_bfloat16 h = __float2bfloat16(v);
        Thz[(size_t)n * ldt + k] = h;
        Tlz[(size_t)n * ldt + k] = __float2bfloat16(v - __bfloat162float(h));
    }
}

__global__ __launch_bounds__(256) void prepass_kernel(
    const float* __restrict__ Xq, const float* __restrict__ Xk,
    const float* __restrict__ Xv,
    const float* __restrict__ WQ, const float* __restrict__ WK,
    const float* __restrict__ WV, const float* __restrict__ WO)
{
    __shared__ float t[32][33];
    const int b = blockIdx.x;

    if (b < PRE_SPLIT3) {
        const float* x;
        __nv_bfloat16 *h, *l;
        int base;
        if (b < 4096)      { x = Xq; h = g_xqh; l = g_xql; base = b; }
        else if (b < 8192) { x = Xk; h = g_xkh; l = g_xkl; base = b - 4096; }
        else               { x = Xv; h = g_xvh; l = g_xvl; base = b - 8192; }
        const int i = (base * 256 + threadIdx.x) * 4;
        float4 v = *(const float4*)(x + i);
        __nv_bfloat16 h0 = __float2bfloat16(v.x);
        __nv_bfloat16 h1 = __float2bfloat16(v.y);
        __nv_bfloat16 h2 = __float2bfloat16(v.z);
        __nv_bfloat16 h3 = __float2bfloat16(v.w);
        *(__nv_bfloat162*)(h + i)     = __nv_bfloat162(h0, h1);
        *(__nv_bfloat162*)(h + i + 2) = __nv_bfloat162(h2, h3);
        *(__nv_bfloat162*)(l + i) =
            __nv_bfloat162(__float2bfloat16(v.x - __bfloat162float(h0)),
                           __float2bfloat16(v.y - __bfloat162float(h1)));
        *(__nv_bfloat162*)(l + i + 2) =
            __nv_bfloat162(__float2bfloat16(v.z - __bfloat162float(h2)),
                           __float2bfloat16(v.w - __bfloat162float(h3)));
    } else if (b < PRE_QKVW) {
        const int bb = b - PRE_SPLIT3;          // 6144 = 4 x 64 x 24
        const int x = bb & 3, y = (bb >> 2) & 63, z = bb >> 8;
        const float* Wz;
        __nv_bfloat16 *Thz, *Tlz;
        if (z < 16) {
            Wz = WQ + (size_t)z * DM * DH;
            Thz = g_wqh + (size_t)z * DH * DM; Tlz = g_wql + (size_t)z * DH * DM;
        } else if (z < 20) {
            const int zz = z - 16;
            Wz = WK + (size_t)zz * DM * DH;
            Thz = g_wkh + (size_t)zz * DH * DM; Tlz = g_wkl + (size_t)zz * DH * DM;
        } else {
            const int zz = z - 20;
            Wz = WV + (size_t)zz * DM * DH;
            Thz = g_wvh + (size_t)zz * DH * DM; Tlz = g_wvl + (size_t)zz * DH * DM;
        }
        transpose_split_body(t, Wz, Thz, Tlz, x * 32, y * 32, DH, DM);
    } else if (b < PRE_WO) {
        const int bb = b - PRE_QKVW;            // 4096 = 64 x 64
        const int x = bb & 63, y = bb >> 6;
        transpose_split_body(t, WO, g_woh, g_wol, x * 32, y * 32, DM, DM);
    } else {
        const int bb = b - PRE_WO;
        const int p = bb * 4 + (threadIdx.x >> 6);
        const int i = threadIdx.x & 63;
        const double freq = exp(9.210340371976184 * ((double)i / 64.0));
        const double ang  = (double)p / freq;
        g_rot[p * 64 + i] = make_float2((float)sin(ang), (float)cos(ang));
    }
}

// ---------------------------------------------------------------------------
// Shared GEMM mainloop: bf16 split-3 HMMA, 2-stage cp.async, ONE sync/step.
// ---------------------------------------------------------------------------
#define RS 80
#define TILE_B (128 * RS)
#define STAGE_B (4 * TILE_B)
#define GEMM_SMEM (2 * STAGE_B)          // 81920; 2 CTAs/SM fits 228KB carveout

static __device__ __forceinline__ void gemm_mainloop(
    uint32_t sb, int tid, int wm, int wn, int lane,
    const __nv_bfloat16* __restrict__ Ah, const __nv_bfloat16* __restrict__ Al,
    const __nv_bfloat16* __restrict__ Bh, const __nv_bfloat16* __restrict__ Bl,
    int mblk, int nblk, int K, float acc[4][4][4])
{
    const int lrow = tid >> 1;
    const int lc0  = (tid & 1) * 2;

    auto load_stage = [&](int ks, int stg) {
        const int k0 = ks * 32;
        const uint32_t base = sb + stg * STAGE_B;
        const size_t aoff = (size_t)(mblk + lrow) * K + k0;
        const size_t boff = (size_t)(nblk + lrow) * K + k0;
        const uint32_t soff = lrow * RS;
#pragma unroll
        for (int j = 0; j < 2; j++) {
            const int c = lc0 + j;
            cp16(base + soff + c * 16,                Ah + aoff + c * 8);
            cp16(base + TILE_B + soff + c * 16,       Al + aoff + c * 8);
            cp16(base + 2 * TILE_B + soff + c * 16,   Bh + boff + c * 8);
            cp16(base + 3 * TILE_B + soff + c * 16,   Bl + boff + c * 8);
        }
        cp_commit();
    };

    const uint32_t a_base = (uint32_t)(wm * 64 + (lane & 15)) * RS + (lane >> 4) * 16;
    const uint32_t b_base = (uint32_t)(wn * 32 + (lane & 7)) * RS + ((lane >> 3) & 1) * 16;

    const int nsteps = K / 32;
    load_stage(0, 0);

    for (int s = 0; s < nsteps; s++) {
        cp_wait<0>();
        __syncthreads();
        if (s + 1 < nsteps) load_stage(s + 1, (s + 1) & 1);

        const uint32_t stg = sb + (s & 1) * STAGE_B;
#pragma unroll
        for (int kf = 0; kf < 2; kf++) {
            const uint32_t ko = kf * 32;
            uint32_t fah[4][4], fal[4][4];
#pragma unroll
            for (int mf = 0; mf < 4; mf++) {
                ldm_x4(fah[mf][0], fah[mf][1], fah[mf][2], fah[mf][3],
                       stg + a_base + mf * (16 * RS) + ko);
                ldm_x4(fal[mf][0], fal[mf][1], fal[mf][2], fal[mf][3],
                       stg + TILE_B + a_base + mf * (16 * RS) + ko);
            }
#pragma unroll
            for (int nf = 0; nf < 4; nf++) {
                uint32_t fbh[2], fbl[2];
                ldm_x2(fbh[0], fbh[1], stg + 2 * TILE_B + b_base + nf * (8 * RS) + ko);
                ldm_x2(fbl[0], fbl[1], stg + 3 * TILE_B + b_base + nf * (8 * RS) + ko);
#pragma unroll
                for (int mf = 0; mf < 4; mf++) mma16816(acc[mf][nf], fah[mf], fbh);
#pragma unroll
                for (int mf = 0; mf < 4; mf++) mma16816(acc[mf][nf], fal[mf], fbh);
#pragma unroll
                for (int mf = 0; mf < 4; mf++) mma16816(acc[mf][nf], fah[mf], fbl);
            }
        }
    }
}

// ---------------------------------------------------------------------------
// Merged Q/K/V projection: grid (16, 1, 24).  minBlocksPerMultiprocessor=2
// caps regs at 128 -> 2 CTAs/SM (reg file was the occupancy limiter).
// ---------------------------------------------------------------------------
__global__ __launch_bounds__(256, 2) void proj_kernel(
    const float* __restrict__ bQ, const float* __restrict__ bK,
    const float* __restrict__ bV)
{
    extern __shared__ char smem[];
    const uint32_t sb = s2u(smem);
    const int tid = threadIdx.x, wid = tid >> 5, lane = tid & 31;
    const int wm = wid >> 2, wn = wid & 3;
    const int mblk = blockIdx.x * 128;
    const int z = blockIdx.z;

    const __nv_bfloat16 *Ah, *Al, *Bh, *Bl;
    const float* bz;
    __nv_bfloat16 *Ch, *Cl;
    int ldc;
    bool rot;
    if (z < 16) {
        Ah = g_xqh; Al = g_xql;
        Bh = g_wqh + (size_t)z * DH * DM; Bl = g_wql + (size_t)z * DH * DM;
        bz = bQ + z * DH; Ch = g_qAh + (size_t)z * DH; Cl = g_qAl + (size_t)z * DH;
        ldc = DM; rot = true;
    } else if (z < 20) {
        const int zz = z - 16;
        Ah = g_xkh; Al = g_xkl;
        Bh = g_wkh + (size_t)zz * DH * DM; Bl = g_wkl + (size_t)zz * DH * DM;
        bz = bK + zz * DH; Ch = g_kAh + (size_t)zz * DH; Cl = g_kAl + (size_t)zz * DH;
        ldc = NKV * DH; rot = true;
    } else {
        const int zz = z - 20;
        Ah = g_xvh; Al = g_xvl;
        Bh = g_wvh + (size_t)zz * DH * DM; Bl = g_wvl + (size_t)zz * DH * DM;
        bz = bV + zz * DH; Ch = g_vAh + (size_t)zz * DH; Cl = g_vAl + (size_t)zz * DH;
        ldc = NKV * DH; rot = false;
    }

    float acc[4][4][4];
#pragma unroll
    for (int i = 0; i < 4; i++)
#pragma unroll
        for (int j = 0; j < 4; j++)
#pragma unroll
            for (int r = 0; r < 4; r++) acc[i][j][r] = 0.f;

    gemm_mainloop(sb, tid, wm, wn, lane, Ah, Al, Bh, Bl, mblk, 0, DM, acc);

    if (rot) {
        float* tile = (float*)smem;
        __syncthreads();
#pragma unroll
        for (int mf = 0; mf < 4; mf++) {
#pragma unroll
            for (int nf = 0; nf < 4; nf++) {
                const int lr = wm * 64 + (lane >> 2) + mf * 16;
                const int lc = wn * 32 + (lane & 3) * 2 + nf * 8;
                const float bx = __ldg(bz + lc), by = __ldg(bz + lc + 1);
                tile[lr * 132 + lc]           = acc[mf][nf][0] + bx;
                tile[lr * 132 + lc + 1]       = acc[mf][nf][1] + by;
                tile[(lr + 8) * 132 + lc]     = acc[mf][nf][2] + bx;
                tile[(lr + 8) * 132 + lc + 1] = acc[mf][nf][3] + by;
            }
        }
        __syncthreads();
        const int row  = tid >> 1;
        const int half = tid & 1;
        const int p    = mblk + row;
        const float* trow = tile + row * 132;
        const size_t gbase = (size_t)p * ldc;
#pragma unroll
        for (int c2 = 0; c2 < 32; c2++) {
            const int i0 = half * 64 + c2 * 2;
            const float2 sc0 = g_rot[p * 64 + (i0 & 63)];
            const float2 sc1 = g_rot[p * 64 + ((i0 + 1) & 63)];
            const float x0 = trow[i0],      x1 = trow[i0 + 1];
            const float y0 = trow[i0 ^ 64], y1 = trow[(i0 + 1) ^ 64];
            const float v0 = half ? (x0 * sc0.y + y0 * sc0.x) : (x0 * sc0.y - y0 * sc0.x);
            const float v1 = half ? (x1 * sc1.y + y1 * sc1.x) : (x1 * sc1.y - y1 * sc1.x);
            const __nv_bfloat16 h0 = __float2bfloat16(v0);
            const __nv_bfloat16 h1 = __float2bfloat16(v1);
            *(__nv_bfloat162*)(Ch + gbase + i0) = __nv_bfloat162(h0, h1);
            *(__nv_bfloat162*)(Cl + gbase + i0) =
                __nv_bfloat162(__float2bfloat16(v0 - __bfloat162float(h0)),
                               __float2bfloat16(v1 - __bfloat162float(h1)));
        }
        return;
    }

    const int r0 = mblk + wm * 64 + (lane >> 2);
    const int c0 = wn * 32 + (lane & 3) * 2;
#pragma unroll
    for (int mf = 0; mf < 4; mf++) {
#pragma unroll
        for (int nf = 0; nf < 4; nf++) {
            const int row = r0 + mf * 16;
            const int col = c0 + nf * 8;
            const float bx = __ldg(bz + col), by = __ldg(bz + col + 1);
            const float v00 = acc[mf][nf][0] + bx, v01 = acc[mf][nf][1] + by;
            const float v10 = acc[mf][nf][2] + bx, v11 = acc[mf][nf][3] + by;
            const __nv_bfloat16 h00 = __float2bfloat16(v00);
            const __nv_bfloat16 h01 = __float2bfloat16(v01);
            const __nv_bfloat16 h10 = __float2bfloat16(v10);
            const __nv_bfloat16 h11 = __float2bfloat16(v11);
            *(__nv_bfloat162*)(Ch + (size_t)row * ldc + col) = __nv_bfloat162(h00, h01);
            *(__nv_bfloat162*)(Ch + (size_t)(row + 8) * ldc + col) = __nv_bfloat162(h10, h11);
            *(__nv_bfloat162*)(Cl + (size_t)row * ldc + col) =
                __nv_bfloat162(__float2bfloat16(v00 - __bfloat162float(h00)),
                               __float2bfloat16(v01 - __bfloat162float(h01)));
            *(__nv_bfloat162*)(Cl + (size_t)(row + 8) * ldc + col) =
                __nv_bfloat162(__float2bfloat16(v10 - __bfloat162float(h10)),
                               __float2bfloat16(v11 - __bfloat162float(h11)));
        }
    }
}

// ---------------------------------------------------------------------------
// Output projection: C[2048,2048] = Z * WO^T + bO (fp32 out).  2 CTAs/SM.
// ---------------------------------------------------------------------------
__global__ __launch_bounds__(256, 2) void wo_gemm_kernel(
    float* __restrict__ C, const float* __restrict__ bias)
{
    extern __shared__ char smem[];
    const uint32_t sb = s2u(smem);
    const int tid = threadIdx.x, wid = tid >> 5, lane = tid & 31;
    const int wm = wid >> 2, wn = wid & 3;
    const int mblk = blockIdx.x * 128, nblk = blockIdx.y * 128;

    float acc[4][4][4];
#pragma unroll
    for (int i = 0; i < 4; i++)
#pragma unroll
        for (int j = 0; j < 4; j++)
#pragma unroll
            for (int r = 0; r < 4; r++) acc[i][j][r] = 0.f;

    gemm_mainloop(sb, tid, wm, wn, lane, g_zh, g_zl, g_woh, g_wol,
                  mblk, nblk, DM, acc);

    const int r0 = mblk + wm * 64 + (lane >> 2);
    const int c0 = nblk + wn * 32 + (lane & 3) * 2;
#pragma unroll
    for (int mf = 0; mf < 4; mf++) {
#pragma unroll
        for (int nf = 0; nf < 4; nf++) {
            const int row = r0 + mf * 16;
            const int col = c0 + nf * 8;
            const float bx = __ldg(bias + col), by = __ldg(bias + col + 1);
            *(float2*)(C + (size_t)row * DM + col) =
                make_float2(acc[mf][nf][0] + bx, acc[mf][nf][1] + by);
            *(float2*)(C + (size_t)(row + 8) * DM + col) =
                make_float2(acc[mf][nf][2] + bx, acc[mf][nf][3] + by);
        }
    }
}

// ---------------------------------------------------------------------------
// Flash attention on mma.sync bf16 split-3.  BQ=128, BK=64, 256 thr (8 warps).
// 1D LPT grid (qb descending primary).
// ---------------------------------------------------------------------------
#define ARS 272
#define AKT (64 * ARS)
#define AQT (128 * ARS)
#define A_SQH 0
#define A_SQL AQT
#define A_KV0 (2 * AQT)
#define A_STG (4 * AKT)
#define ATTN_SMEM (A_KV0 + 2 * A_STG)    // 208896

__global__ __launch_bounds__(256) void attn_mma_kernel()
{
    extern __shared__ char smem[];
    const uint32_t sb = s2u(smem);
    const int tid  = threadIdx.x;
    const int lane = tid & 31;
    const int wq   = tid >> 5;
    const int rank = blockIdx.x;
    const int qb   = 15 - (rank >> 4);
    const int h    = rank & 15;
    const int kvh  = h >> 2;
    const int q0   = qb * 128;

    {
        const int row = tid >> 1;
        const int cb  = (tid & 1) * 8;
        const size_t goff = (size_t)(q0 + row) * DM + h * DH;
#pragma unroll
        for (int j = 0; j < 8; j++) {
            const int c = cb + j;
            cp16(sb + A_SQH + row * ARS + c * 16, g_qAh + goff + c * 8);
            cp16(sb + A_SQL + row * ARS + c * 16, g_qAl + goff + c * 8);
        }
        cp_commit();
    }

    auto load_kv = [&](int kb, int stg) {
        const uint32_t base = sb + A_KV0 + stg * A_STG;
        const int row = tid >> 2;
        const int cb  = (tid & 3) * 4;
        const size_t goff = (size_t)(kb * 64 + row) * (NKV * DH) + kvh * DH;
#pragma unroll
        for (int j = 0; j < 4; j++) {
            const int c = cb + j;
            cp16(base + 0 * AKT + row * ARS + c * 16, g_kAh + goff + c * 8);
            cp16(base + 1 * AKT + row * ARS + c * 16, g_kAl + goff + c * 8);
            cp16(base + 2 * AKT + row * ARS + c * 16, g_vAh + goff + c * 8);
            cp16(base + 3 * AKT + row * ARS + c * 16, g_vAl + goff + c * 8);
        }
        cp_commit();
    };
    load_kv(0, 0);

    float o[16][4];
#pragma unroll
    for (int i = 0; i < 16; i++)
#pragma unroll
        for (int r = 0; r < 4; r++) o[i][r] = 0.f;
    float m0 = -INFINITY, m1 = -INFINITY, l0 = 0.f, l1 = 0.f;

    const uint32_t frag_row = (uint32_t)((lane & 7) + ((lane >> 3) & 1) * 8) * ARS;
    const uint32_t frag_col = ((lane >> 4) & 1) * 16;
    const float SCL = 0.08838834764831845f * 1.4426950408889634f;

    const int nkb = 2 * qb + 2;
    for (int kb = 0; kb < nkb; kb++) {
        cp_wait<0>();
        __syncthreads();
        if (kb + 1 < nkb) load_kv(kb + 1, (kb + 1) & 1);

        const uint32_t skv = sb + A_KV0 + (kb & 1) * A_STG;

        float sc[8][4];
#pragma unroll
        for (int i = 0; i < 8; i++)
#pragma unroll
            for (int r = 0; r < 4; r++) sc[i][r] = 0.f;

#pragma unroll
        for (int ks = 0; ks < 8; ks++) {
            const uint32_t qoff = (uint32_t)(wq * 16) * ARS + frag_row + ks * 32 + frag_col;
            uint32_t qh[4], ql[4];
            ldm_x4(qh[0], qh[1], qh[2], qh[3], sb + A_SQH + qoff);
            ldm_x4(ql[0], ql[1], ql[2], ql[3], sb + A_SQL + qoff);
#pragma unroll
            for (int np = 0; np < 4; np++) {
                const uint32_t koff = (uint32_t)(np * 16) * ARS + frag_row + ks * 32 + frag_col;
                uint32_t kh[4], kl[4];
                ldm_x4(kh[0], kh[1], kh[2], kh[3], skv + 0 * AKT + koff);
                ldm_x4(kl[0], kl[1], kl[2], kl[3], skv + 1 * AKT + koff);
                uint32_t bh0[2] = {kh[0], kh[2]}, bh1[2] = {kh[1], kh[3]};
                uint32_t bl0[2] = {kl[0], kl[2]}, bl1[2] = {kl[1], kl[3]};
                mma16816(sc[2 * np],     qh, bh0);
                mma16816(sc[2 * np],     qh, bl0);
                mma16816(sc[2 * np],     ql, bh0);
                mma16816(sc[2 * np + 1], qh, bh1);
                mma16816(sc[2 * np + 1], qh, bl1);
                mma16816(sc[2 * np + 1], ql, bh1);
            }
        }

        const int rg0 = q0 + wq * 16 + (lane >> 2);
        const int rg1 = rg0 + 8;
        const bool diag = (kb >= 2 * qb);
        float mx0 = -INFINITY, mx1 = -INFINITY;
#pragma unroll
        for (int nf = 0; nf < 8; nf++) {
            float t0 = sc[nf][0] * SCL, t1 = sc[nf][1] * SCL;
            float t2 = sc[nf][2] * SCL, t3 = sc[nf][3] * SCL;
            if (diag) {
                const int col = kb * 64 + nf * 8 + (lane & 3) * 2;
                if (col     > rg0) t0 = -INFINITY;
                if (col + 1 > rg0) t1 = -INFINITY;
                if (col     > rg1) t2 = -INFINITY;
                if (col + 1 > rg1) t3 = -INFINITY;
            }
            sc[nf][0] = t0; sc[nf][1] = t1; sc[nf][2] = t2; sc[nf][3] = t3;
            mx0 = fmaxf(mx0, fmaxf(t0, t1));
            mx1 = fmaxf(mx1, fmaxf(t2, t3));
        }
        mx0 = fmaxf(mx0, __shfl_xor_sync(0xffffffffu, mx0, 1));
        mx0 = fmaxf(mx0, __shfl_xor_sync(0xffffffffu, mx0, 2));
        mx1 = fmaxf(mx1, __shfl_xor_sync(0xffffffffu, mx1, 1));
        mx1 = fmaxf(mx1, __shfl_xor_sync(0xffffffffu, mx1, 2));
        const float mn0 = fmaxf(m0, mx0), mn1 = fmaxf(m1, mx1);
        const float corr0 = exp2f(m0 - mn0), corr1 = exp2f(m1 - mn1);
        m0 = mn0; m1 = mn1;

        float rs0 = 0.f, rs1 = 0.f;
#pragma unroll
        for (int nf = 0; nf < 8; nf++) {
            float p0 = exp2f(sc[nf][0] - mn0);
            float p1 = exp2f(sc[nf][1] - mn0);
            float p2 = exp2f(sc[nf][2] - mn1);
            float p3 = exp2f(sc[nf][3] - mn1);
            sc[nf][0] = p0; sc[nf][1] = p1; sc[nf][2] = p2; sc[nf][3] = p3;
            rs0 += p0 + p1; rs1 += p2 + p3;
        }
        rs0 += __shfl_xor_sync(0xffffffffu, rs0, 1);
        rs0 += __shfl_xor_sync(0xffffffffu, rs0, 2);
        rs1 += __shfl_xor_sync(0xffffffffu, rs1, 1);
        rs1 += __shfl_xor_sync(0xffffffffu, rs1, 2);
        l0 = l0 * corr0 + rs0;
        l1 = l1 * corr1 + rs1;
#pragma unroll
        for (int i = 0; i < 16; i++) {
            o[i][0] *= corr0; o[i][1] *= corr0;
            o[i][2] *= corr1; o[i][3] *= corr1;
        }

        uint32_t pAh[4][4], pAl[4][4];
#pragma unroll
        for (int kg = 0; kg < 4; kg++) {
            const float c0 = sc[2 * kg][0], c1 = sc[2 * kg][1];
            const float c2 = sc[2 * kg][2], c3 = sc[2 * kg][3];
            const float d0 = sc[2 * kg + 1][0], d1 = sc[2 * kg + 1][1];
            const float d2 = sc[2 * kg + 1][2], d3 = sc[2 * kg + 1][3];
            pAh[kg][0] = packbf(c0, c1);
            pAh[kg][1] = packbf(c2, c3);
            pAh[kg][2] = packbf(d0, d1);
            pAh[kg][3] = packbf(d2, d3);
            pAl[kg][0] = packbf(c0 - __bfloat162float(__float2bfloat16(c0)),
                                c1 - __bfloat162float(__float2bfloat16(c1)));
            pAl[kg][1] = packbf(c2 - __bfloat162float(__float2bfloat16(c2)),
                                c3 - __bfloat162float(__float2bfloat16(c3)));
            pAl[kg][2] = packbf(d0 - __bfloat162float(__float2bfloat16(d0)),
                                d1 - __bfloat162float(__float2bfloat16(d1)));
            pAl[kg][3] = packbf(d2 - __bfloat162float(__float2bfloat16(d2)),
                                d3 - __bfloat162float(__float2bfloat16(d3)));
        }

#pragma unroll
        for (int dg = 0; dg < 8; dg++) {
#pragma unroll
            for (int kg = 0; kg < 4; kg++) {
                const uint32_t voff = (uint32_t)(kg * 16) * ARS + frag_row + dg * 32 + frag_col;
                uint32_t vh[4], vl[4];
                ldm_x4_t(vh[0], vh[1], vh[2], vh[3], skv + 2 * AKT + voff);
                ldm_x4_t(vl[0], vl[1], vl[2], vl[3], skv + 3 * AKT + voff);
                uint32_t bh0[2] = {vh[0], vh[1]}, bh1[2] = {vh[2], vh[3]};
                uint32_t bl0[2] = {vl[0], vl[1]}, bl1[2] = {vl[2], vl[3]};
                mma16816(o[2 * dg],     pAh[kg], bh0);
                mma16816(o[2 * dg],     pAh[kg], bl0);
                mma16816(o[2 * dg],     pAl[kg], bh0);
                mma16816(o[2 * dg + 1], pAh[kg], bh1);
                mma16816(o[2 * dg + 1], pAh[kg], bl1);
                mma16816(o[2 * dg + 1], pAl[kg], bh1);
            }
        }
    }

    const float inv0 = 1.f / l0, inv1 = 1.f / l1;
    const int rg0 = q0 + wq * 16 + (lane >> 2);
#pragma unroll
    for (int nf = 0; nf < 16; nf++) {
        const int col = h * DH + nf * 8 + (lane & 3) * 2;
        const float a0 = o[nf][0] * inv0, a1 = o[nf][1] * inv0;
        const float a2 = o[nf][2] * inv1, a3 = o[nf][3] * inv1;
        const __nv_bfloat16 h0 = __float2bfloat16(a0), h1 = __float2bfloat16(a1);
        const __nv_bfloat16 h2 = __float2bfloat16(a2), h3 = __float2bfloat16(a3);
        const size_t b0 = (size_t)rg0 * DM + col;
        const size_t b1 = (size_t)(rg0 + 8) * DM + col;
        *(__nv_bfloat162*)(g_zh + b0) = __nv_bfloat162(h0, h1);
        *(__nv_bfloat162*)(g_zh + b1) = __nv_bfloat162(h2, h3);
        *(__nv_bfloat162*)(g_zl + b0) =
            __nv_bfloat162(__float2bfloat16(a0 - __bfloat162float(h0)),
                           __float2bfloat16(a1 - __bfloat162float(h1)));
        *(__nv_bfloat162*)(g_zl + b1) =
            __nv_bfloat162(__float2bfloat16(a2 - __bfloat162float(h2)),
                           __float2bfloat16(a3 - __bfloat162float(h3)));
    }
}

// ---------------------------------------------------------------------------
extern "C" void kernel_launch(void* const* d_in, const int* in_sizes, int n_in,
                              void* d_out, int out_size)
{
    const float* Xq = (const float*)d_in[0];
    const float* Xk = (const float*)d_in[1];
    const float* Xv = (const float*)d_in[2];
    const float* WQ = (const float*)d_in[3];
    const float* bQ = (const float*)d_in[4];
    const float* WK = (const float*)d_in[5];
    const float* bK = (const float*)d_in[6];
    const float* WV = (const float*)d_in[7];
    const float* bV = (const float*)d_in[8];
    const float* WO = (const float*)d_in[9];
    const float* bO = (const float*)d_in[10];
    float* out = (float*)d_out;

    cudaFuncSetAttribute(proj_kernel,
                         cudaFuncAttributeMaxDynamicSharedMemorySize, GEMM_SMEM);
    cudaFuncSetAttribute(wo_gemm_kernel,
                         cudaFuncAttributeMaxDynamicSharedMemorySize, GEMM_SMEM);
    cudaFuncSetAttribute(attn_mma_kernel,
                         cudaFuncAttributeMaxDynamicSharedMemorySize, ATTN_SMEM);

    prepass_kernel<<<PRE_TOTAL, 256>>>(Xq, Xk, Xv, WQ, WK, WV, WO);

    proj_kernel<<<dim3(16, 1, 24), 256, GEMM_SMEM>>>(bQ, bK, bV);

    attn_mma_kernel<<<256, 256, ATTN_SMEM>>>();

    wo_gemm_kernel<<<dim3(16, 16, 1), 256, GEMM_SMEM>>>(out, bO);
}

// round 17
// speedup vs baseline: 1.1362x; 1.1362x over previous
#include <cuda_runtime.h>
#include <cuda_bf16.h>
#include <cstdint>
#include <math.h>
#include <float.h>

#define SLEN 2048
#define DM   2048
#define NH   16
#define NKV  4
#define DH   128

// ---------------- scratch (__device__ globals; no allocs allowed) ----------
__device__ float2 g_rot[SLEN * 64];

__device__ __nv_bfloat16 g_xqh[SLEN * DM], g_xql[SLEN * DM];
__device__ __nv_bfloat16 g_xkh[SLEN * DM], g_xkl[SLEN * DM];
__device__ __nv_bfloat16 g_xvh[SLEN * DM], g_xvl[SLEN * DM];
__device__ __nv_bfloat16 g_zh [SLEN * DM], g_zl [SLEN * DM];
__device__ __nv_bfloat16 g_wqh[NH  * DH * DM], g_wql[NH  * DH * DM];
__device__ __nv_bfloat16 g_wkh[NKV * DH * DM], g_wkl[NKV * DH * DM];
__device__ __nv_bfloat16 g_wvh[NKV * DH * DM], g_wvl[NKV * DH * DM];
__device__ __nv_bfloat16 g_woh[DM * DM],       g_wol[DM * DM];
__device__ __nv_bfloat16 g_qAh[SLEN * DM],        g_qAl[SLEN * DM];
__device__ __nv_bfloat16 g_kAh[SLEN * NKV * DH],  g_kAl[SLEN * NKV * DH];
__device__ __nv_bfloat16 g_vAh[SLEN * NKV * DH],  g_vAl[SLEN * NKV * DH];

// ---------------- helpers (sm_80-level features only) ----------------------
static __device__ __forceinline__ uint32_t s2u(const void* p) {
    uint32_t a;
    asm("{ .reg .u64 t; cvta.to.shared.u64 t, %1; cvt.u32.u64 %0, t; }"
        : "=r"(a) : "l"(p));
    return a;
}
static __device__ __forceinline__ void cp16(uint32_t dst, const void* src) {
    asm volatile("cp.async.cg.shared.global [%0], [%1], 16;"
                 :: "r"(dst), "l"(src) : "memory");
}
static __device__ __forceinline__ void cp_commit() {
    asm volatile("cp.async.commit_group;" ::: "memory");
}
template <int N>
static __device__ __forceinline__ void cp_wait() {
    asm volatile("cp.async.wait_group %0;" :: "n"(N) : "memory");
}
static __device__ __forceinline__ void ldm_x4(uint32_t& r0, uint32_t& r1,
                                              uint32_t& r2, uint32_t& r3, uint32_t a) {
    asm volatile("ldmatrix.sync.aligned.m8n8.x4.shared.b16 {%0,%1,%2,%3}, [%4];"
                 : "=r"(r0), "=r"(r1), "=r"(r2), "=r"(r3) : "r"(a));
}
static __device__ __forceinline__ void ldm_x4_t(uint32_t& r0, uint32_t& r1,
                                                uint32_t& r2, uint32_t& r3, uint32_t a) {
    asm volatile("ldmatrix.sync.aligned.m8n8.x4.trans.shared.b16 {%0,%1,%2,%3}, [%4];"
                 : "=r"(r0), "=r"(r1), "=r"(r2), "=r"(r3) : "r"(a));
}
static __device__ __forceinline__ void ldm_x2(uint32_t& r0, uint32_t& r1, uint32_t a) {
    asm volatile("ldmatrix.sync.aligned.m8n8.x2.shared.b16 {%0,%1}, [%2];"
                 : "=r"(r0), "=r"(r1) : "r"(a));
}
static __device__ __forceinline__ void mma16816(float* d, const uint32_t* a,
                                                const uint32_t* b) {
    asm volatile(
        "mma.sync.aligned.m16n8k16.row.col.f32.bf16.bf16.f32 "
        "{%0,%1,%2,%3}, {%4,%5,%6,%7}, {%8,%9}, {%0,%1,%2,%3};"
        : "+f"(d[0]), "+f"(d[1]), "+f"(d[2]), "+f"(d[3])
        : "r"(a[0]), "r"(a[1]), "r"(a[2]), "r"(a[3]), "r"(b[0]), "r"(b[1]));
}
static __device__ __forceinline__ uint32_t packbf(float x, float y) {
    __nv_bfloat162 t = __floats2bfloat162_rn(x, y);
    return *(uint32_t*)&t;
}

// ---------------------------------------------------------------------------
// Merged pre-pass (single launch, range-dispatched over 1D grid).
// ---------------------------------------------------------------------------
#define PRE_SPLIT3 12288
#define PRE_QKVW   (PRE_SPLIT3 + 6144)
#define PRE_WO     (PRE_QKVW + 4096)
#define PRE_TOTAL  (PRE_WO + 512)

static __device__ __forceinline__ void transpose_split_body(
    float t[32][33], const float* __restrict__ Wz,
    __nv_bfloat16* __restrict__ Thz, __nv_bfloat16* __restrict__ Tlz,
    int n0, int k0, int ldw, int ldt)
{
    const int tx = threadIdx.x & 31, ty = threadIdx.x >> 5;
#pragma unroll
    for (int r = 0; r < 4; r++)
        t[ty + 8 * r][tx] = Wz[(size_t)(k0 + ty + 8 * r) * ldw + n0 + tx];
    __syncthreads();
#pragma unroll
    for (int r = 0; r < 4; r++) {
        int n = n0 + ty + 8 * r, k = k0 + tx;
        float v = t[tx][ty + 8 * r];
        __nv_bfloat16 h = __float2bfloat16(v);
        Thz[(size_t)n * ldt + k] = h;
        Tlz[(size_t)n * ldt + k] = __float2bfloat16(v - __bfloat162float(h));
    }
}

__global__ __launch_bounds__(256) void prepass_kernel(
    const float* __restrict__ Xq, const float* __restrict__ Xk,
    const float* __restrict__ Xv,
    const float* __restrict__ WQ, const float* __restrict__ WK,
    const float* __restrict__ WV, const float* __restrict__ WO)
{
    __shared__ float t[32][33];
    const int b = blockIdx.x;

    if (b < PRE_SPLIT3) {
        const float* x;
        __nv_bfloat16 *h, *l;
        int base;
        if (b < 4096)      { x = Xq; h = g_xqh; l = g_xql; base = b; }
        else if (b < 8192) { x = Xk; h = g_xkh; l = g_xkl; base = b - 4096; }
        else               { x = Xv; h = g_xvh; l = g_xvl; base = b - 8192; }
        const int i = (base * 256 + threadIdx.x) * 4;
        float4 v = *(const float4*)(x + i);
        __nv_bfloat16 h0 = __float2bfloat16(v.x);
        __nv_bfloat16 h1 = __float2bfloat16(v.y);
        __nv_bfloat16 h2 = __float2bfloat16(v.z);
        __nv_bfloat16 h3 = __float2bfloat16(v.w);
        *(__nv_bfloat162*)(h + i)     = __nv_bfloat162(h0, h1);
        *(__nv_bfloat162*)(h + i + 2) = __nv_bfloat162(h2, h3);
        *(__nv_bfloat162*)(l + i) =
            __nv_bfloat162(__float2bfloat16(v.x - __bfloat162float(h0)),
                           __float2bfloat16(v.y - __bfloat162float(h1)));
        *(__nv_bfloat162*)(l + i + 2) =
            __nv_bfloat162(__float2bfloat16(v.z - __bfloat162float(h2)),
                           __float2bfloat16(v.w - __bfloat162float(h3)));
    } else if (b < PRE_QKVW) {
        const int bb = b - PRE_SPLIT3;          // 6144 = 4 x 64 x 24
        const int x = bb & 3, y = (bb >> 2) & 63, z = bb >> 8;
        const float* Wz;
        __nv_bfloat16 *Thz, *Tlz;
        if (z < 16) {
            Wz = WQ + (size_t)z * DM * DH;
            Thz = g_wqh + (size_t)z * DH * DM; Tlz = g_wql + (size_t)z * DH * DM;
        } else if (z < 20) {
            const int zz = z - 16;
            Wz = WK + (size_t)zz * DM * DH;
            Thz = g_wkh + (size_t)zz * DH * DM; Tlz = g_wkl + (size_t)zz * DH * DM;
        } else {
            const int zz = z - 20;
            Wz = WV + (size_t)zz * DM * DH;
            Thz = g_wvh + (size_t)zz * DH * DM; Tlz = g_wvl + (size_t)zz * DH * DM;
        }
        transpose_split_body(t, Wz, Thz, Tlz, x * 32, y * 32, DH, DM);
    } else if (b < PRE_WO) {
        const int bb = b - PRE_QKVW;            // 4096 = 64 x 64
        const int x = bb & 63, y = bb >> 6;
        transpose_split_body(t, WO, g_woh, g_wol, x * 32, y * 32, DM, DM);
    } else {
        const int bb = b - PRE_WO;
        const int p = bb * 4 + (threadIdx.x >> 6);
        const int i = threadIdx.x & 63;
        const double freq = exp(9.210340371976184 * ((double)i / 64.0));
        const double ang  = (double)p / freq;
        g_rot[p * 64 + i] = make_float2((float)sin(ang), (float)cos(ang));
    }
}

// ---------------------------------------------------------------------------
// Shared GEMM mainloop: bf16 split-3 HMMA, 2-stage cp.async, ONE sync/step.
// ---------------------------------------------------------------------------
#define RS 80
#define TILE_B (128 * RS)
#define STAGE_B (4 * TILE_B)
#define GEMM_SMEM (2 * STAGE_B)          // 81920

static __device__ __forceinline__ void gemm_mainloop(
    uint32_t sb, int tid, int wm, int wn, int lane,
    const __nv_bfloat16* __restrict__ Ah, const __nv_bfloat16* __restrict__ Al,
    const __nv_bfloat16* __restrict__ Bh, const __nv_bfloat16* __restrict__ Bl,
    int mblk, int nblk, int K, float acc[4][4][4])
{
    const int lrow = tid >> 1;
    const int lc0  = (tid & 1) * 2;

    auto load_stage = [&](int ks, int stg) {
        const int k0 = ks * 32;
        const uint32_t base = sb + stg * STAGE_B;
        const size_t aoff = (size_t)(mblk + lrow) * K + k0;
        const size_t boff = (size_t)(nblk + lrow) * K + k0;
        const uint32_t soff = lrow * RS;
#pragma unroll
        for (int j = 0; j < 2; j++) {
            const int c = lc0 + j;
            cp16(base + soff + c * 16,                Ah + aoff + c * 8);
            cp16(base + TILE_B + soff + c * 16,       Al + aoff + c * 8);
            cp16(base + 2 * TILE_B + soff + c * 16,   Bh + boff + c * 8);
            cp16(base + 3 * TILE_B + soff + c * 16,   Bl + boff + c * 8);
        }
        cp_commit();
    };

    const uint32_t a_base = (uint32_t)(wm * 64 + (lane & 15)) * RS + (lane >> 4) * 16;
    const uint32_t b_base = (uint32_t)(wn * 32 + (lane & 7)) * RS + ((lane >> 3) & 1) * 16;

    const int nsteps = K / 32;
    load_stage(0, 0);

    for (int s = 0; s < nsteps; s++) {
        cp_wait<0>();
        __syncthreads();
        if (s + 1 < nsteps) load_stage(s + 1, (s + 1) & 1);

        const uint32_t stg = sb + (s & 1) * STAGE_B;
#pragma unroll
        for (int kf = 0; kf < 2; kf++) {
            const uint32_t ko = kf * 32;
            uint32_t fah[4][4], fal[4][4];
#pragma unroll
            for (int mf = 0; mf < 4; mf++) {
                ldm_x4(fah[mf][0], fah[mf][1], fah[mf][2], fah[mf][3],
                       stg + a_base + mf * (16 * RS) + ko);
                ldm_x4(fal[mf][0], fal[mf][1], fal[mf][2], fal[mf][3],
                       stg + TILE_B + a_base + mf * (16 * RS) + ko);
            }
#pragma unroll
            for (int nf = 0; nf < 4; nf++) {
                uint32_t fbh[2], fbl[2];
                ldm_x2(fbh[0], fbh[1], stg + 2 * TILE_B + b_base + nf * (8 * RS) + ko);
                ldm_x2(fbl[0], fbl[1], stg + 3 * TILE_B + b_base + nf * (8 * RS) + ko);
#pragma unroll
                for (int mf = 0; mf < 4; mf++) mma16816(acc[mf][nf], fah[mf], fbh);
#pragma unroll
                for (int mf = 0; mf < 4; mf++) mma16816(acc[mf][nf], fal[mf], fbh);
#pragma unroll
                for (int mf = 0; mf < 4; mf++) mma16816(acc[mf][nf], fah[mf], fbl);
            }
        }
    }
}

// ---------------------------------------------------------------------------
// Merged Q/K/V projection: grid (16, 1, 24).  NO reg cap (the R16 cap spilled
// the rotary epilogue); codegen matches the proven R15 binary.
// ---------------------------------------------------------------------------
__global__ __launch_bounds__(256) void proj_kernel(
    const float* __restrict__ bQ, const float* __restrict__ bK,
    const float* __restrict__ bV)
{
    extern __shared__ char smem[];
    const uint32_t sb = s2u(smem);
    const int tid = threadIdx.x, wid = tid >> 5, lane = tid & 31;
    const int wm = wid >> 2, wn = wid & 3;
    const int mblk = blockIdx.x * 128;
    const int z = blockIdx.z;

    const __nv_bfloat16 *Ah, *Al, *Bh, *Bl;
    const float* bz;
    __nv_bfloat16 *Ch, *Cl;
    int ldc;
    bool rot;
    if (z < 16) {
        Ah = g_xqh; Al = g_xql;
        Bh = g_wqh + (size_t)z * DH * DM; Bl = g_wql + (size_t)z * DH * DM;
        bz = bQ + z * DH; Ch = g_qAh + (size_t)z * DH; Cl = g_qAl + (size_t)z * DH;
        ldc = DM; rot = true;
    } else if (z < 20) {
        const int zz = z - 16;
        Ah = g_xkh; Al = g_xkl;
        Bh = g_wkh + (size_t)zz * DH * DM; Bl = g_wkl + (size_t)zz * DH * DM;
        bz = bK + zz * DH; Ch = g_kAh + (size_t)zz * DH; Cl = g_kAl + (size_t)zz * DH;
        ldc = NKV * DH; rot = true;
    } else {
        const int zz = z - 20;
        Ah = g_xvh; Al = g_xvl;
        Bh = g_wvh + (size_t)zz * DH * DM; Bl = g_wvl + (size_t)zz * DH * DM;
        bz = bV + zz * DH; Ch = g_vAh + (size_t)zz * DH; Cl = g_vAl + (size_t)zz * DH;
        ldc = NKV * DH; rot = false;
    }

    float acc[4][4][4];
#pragma unroll
    for (int i = 0; i < 4; i++)
#pragma unroll
        for (int j = 0; j < 4; j++)
#pragma unroll
            for (int r = 0; r < 4; r++) acc[i][j][r] = 0.f;

    gemm_mainloop(sb, tid, wm, wn, lane, Ah, Al, Bh, Bl, mblk, 0, DM, acc);

    if (rot) {
        float* tile = (float*)smem;
        __syncthreads();
#pragma unroll
        for (int mf = 0; mf < 4; mf++) {
#pragma unroll
            for (int nf = 0; nf < 4; nf++) {
                const int lr = wm * 64 + (lane >> 2) + mf * 16;
                const int lc = wn * 32 + (lane & 3) * 2 + nf * 8;
                const float bx = __ldg(bz + lc), by = __ldg(bz + lc + 1);
                tile[lr * 132 + lc]           = acc[mf][nf][0] + bx;
                tile[lr * 132 + lc + 1]       = acc[mf][nf][1] + by;
                tile[(lr + 8) * 132 + lc]     = acc[mf][nf][2] + bx;
                tile[(lr + 8) * 132 + lc + 1] = acc[mf][nf][3] + by;
            }
        }
        __syncthreads();
        const int row  = tid >> 1;
        const int half = tid & 1;
        const int p    = mblk + row;
        const float* trow = tile + row * 132;
        const size_t gbase = (size_t)p * ldc;
#pragma unroll
        for (int c2 = 0; c2 < 32; c2++) {
            const int i0 = half * 64 + c2 * 2;
            const float2 sc0 = g_rot[p * 64 + (i0 & 63)];
            const float2 sc1 = g_rot[p * 64 + ((i0 + 1) & 63)];
            const float x0 = trow[i0],      x1 = trow[i0 + 1];
            const float y0 = trow[i0 ^ 64], y1 = trow[(i0 + 1) ^ 64];
            const float v0 = half ? (x0 * sc0.y + y0 * sc0.x) : (x0 * sc0.y - y0 * sc0.x);
            const float v1 = half ? (x1 * sc1.y + y1 * sc1.x) : (x1 * sc1.y - y1 * sc1.x);
            const __nv_bfloat16 h0 = __float2bfloat16(v0);
            const __nv_bfloat16 h1 = __float2bfloat16(v1);
            *(__nv_bfloat162*)(Ch + gbase + i0) = __nv_bfloat162(h0, h1);
            *(__nv_bfloat162*)(Cl + gbase + i0) =
                __nv_bfloat162(__float2bfloat16(v0 - __bfloat162float(h0)),
                               __float2bfloat16(v1 - __bfloat162float(h1)));
        }
        return;
    }

    const int r0 = mblk + wm * 64 + (lane >> 2);
    const int c0 = wn * 32 + (lane & 3) * 2;
#pragma unroll
    for (int mf = 0; mf < 4; mf++) {
#pragma unroll
        for (int nf = 0; nf < 4; nf++) {
            const int row = r0 + mf * 16;
            const int col = c0 + nf * 8;
            const float bx = __ldg(bz + col), by = __ldg(bz + col + 1);
            const float v00 = acc[mf][nf][0] + bx, v01 = acc[mf][nf][1] + by;
            const float v10 = acc[mf][nf][2] + bx, v11 = acc[mf][nf][3] + by;
            const __nv_bfloat16 h00 = __float2bfloat16(v00);
            const __nv_bfloat16 h01 = __float2bfloat16(v01);
            const __nv_bfloat16 h10 = __float2bfloat16(v10);
            const __nv_bfloat16 h11 = __float2bfloat16(v11);
            *(__nv_bfloat162*)(Ch + (size_t)row * ldc + col) = __nv_bfloat162(h00, h01);
            *(__nv_bfloat162*)(Ch + (size_t)(row + 8) * ldc + col) = __nv_bfloat162(h10, h11);
            *(__nv_bfloat162*)(Cl + (size_t)row * ldc + col) =
                __nv_bfloat162(__float2bfloat16(v00 - __bfloat162float(h00)),
                               __float2bfloat16(v01 - __bfloat162float(h01)));
            *(__nv_bfloat162*)(Cl + (size_t)(row + 8) * ldc + col) =
                __nv_bfloat162(__float2bfloat16(v10 - __bfloat162float(h10)),
                               __float2bfloat16(v11 - __bfloat162float(h11)));
        }
    }
}

// ---------------------------------------------------------------------------
// Output projection: C[2048,2048] = Z * WO^T + bO.  Reg-capped: 2 CTAs/SM
// (no epilogue pressure here; R16 measured 225 -> 204 us with this cap).
// ---------------------------------------------------------------------------
__global__ __launch_bounds__(256, 2) void wo_gemm_kernel(
    float* __restrict__ C, const float* __restrict__ bias)
{
    extern __shared__ char smem[];
    const uint32_t sb = s2u(smem);
    const int tid = threadIdx.x, wid = tid >> 5, lane = tid & 31;
    const int wm = wid >> 2, wn = wid & 3;
    const int mblk = blockIdx.x * 128, nblk = blockIdx.y * 128;

    float acc[4][4][4];
#pragma unroll
    for (int i = 0; i < 4; i++)
#pragma unroll
        for (int j = 0; j < 4; j++)
#pragma unroll
            for (int r = 0; r < 4; r++) acc[i][j][r] = 0.f;

    gemm_mainloop(sb, tid, wm, wn, lane, g_zh, g_zl, g_woh, g_wol,
                  mblk, nblk, DM, acc);

    const int r0 = mblk + wm * 64 + (lane >> 2);
    const int c0 = nblk + wn * 32 + (lane & 3) * 2;
#pragma unroll
    for (int mf = 0; mf < 4; mf++) {
#pragma unroll
        for (int nf = 0; nf < 4; nf++) {
            const int row = r0 + mf * 16;
            const int col = c0 + nf * 8;
            const float bx = __ldg(bias + col), by = __ldg(bias + col + 1);
            *(float2*)(C + (size_t)row * DM + col) =
                make_float2(acc[mf][nf][0] + bx, acc[mf][nf][1] + by);
            *(float2*)(C + (size_t)(row + 8) * DM + col) =
                make_float2(acc[mf][nf][2] + bx, acc[mf][nf][3] + by);
        }
    }
}

// ---------------------------------------------------------------------------
// Flash attention on mma.sync bf16 split-3.  BQ=128, BK=64, 256 thr (8 warps).
// 1D LPT grid (qb descending primary).
// ---------------------------------------------------------------------------
#define ARS 272
#define AKT (64 * ARS)
#define AQT (128 * ARS)
#define A_SQH 0
#define A_SQL AQT
#define A_KV0 (2 * AQT)
#define A_STG (4 * AKT)
#define ATTN_SMEM (A_KV0 + 2 * A_STG)    // 208896

__global__ __launch_bounds__(256) void attn_mma_kernel()
{
    extern __shared__ char smem[];
    const uint32_t sb = s2u(smem);
    const int tid  = threadIdx.x;
    const int lane = tid & 31;
    const int wq   = tid >> 5;
    const int rank = blockIdx.x;
    const int qb   = 15 - (rank >> 4);
    const int h    = rank & 15;
    const int kvh  = h >> 2;
    const int q0   = qb * 128;

    {
        const int row = tid >> 1;
        const int cb  = (tid & 1) * 8;
        const size_t goff = (size_t)(q0 + row) * DM + h * DH;
#pragma unroll
        for (int j = 0; j < 8; j++) {
            const int c = cb + j;
            cp16(sb + A_SQH + row * ARS + c * 16, g_qAh + goff + c * 8);
            cp16(sb + A_SQL + row * ARS + c * 16, g_qAl + goff + c * 8);
        }
        cp_commit();
    }

    auto load_kv = [&](int kb, int stg) {
        const uint32_t base = sb + A_KV0 + stg * A_STG;
        const int row = tid >> 2;
        const int cb  = (tid & 3) * 4;
        const size_t goff = (size_t)(kb * 64 + row) * (NKV * DH) + kvh * DH;
#pragma unroll
        for (int j = 0; j < 4; j++) {
            const int c = cb + j;
            cp16(base + 0 * AKT + row * ARS + c * 16, g_kAh + goff + c * 8);
            cp16(base + 1 * AKT + row * ARS + c * 16, g_kAl + goff + c * 8);
            cp16(base + 2 * AKT + row * ARS + c * 16, g_vAh + goff + c * 8);
            cp16(base + 3 * AKT + row * ARS + c * 16, g_vAl + goff + c * 8);
        }
        cp_commit();
    };
    load_kv(0, 0);

    float o[16][4];
#pragma unroll
    for (int i = 0; i < 16; i++)
#pragma unroll
        for (int r = 0; r < 4; r++) o[i][r] = 0.f;
    float m0 = -INFINITY, m1 = -INFINITY, l0 = 0.f, l1 = 0.f;

    const uint32_t frag_row = (uint32_t)((lane & 7) + ((lane >> 3) & 1) * 8) * ARS;
    const uint32_t frag_col = ((lane >> 4) & 1) * 16;
    const float SCL = 0.08838834764831845f * 1.4426950408889634f;

    const int nkb = 2 * qb + 2;
    for (int kb = 0; kb < nkb; kb++) {
        cp_wait<0>();
        __syncthreads();
        if (kb + 1 < nkb) load_kv(kb + 1, (kb + 1) & 1);

        const uint32_t skv = sb + A_KV0 + (kb & 1) * A_STG;

        float sc[8][4];
#pragma unroll
        for (int i = 0; i < 8; i++)
#pragma unroll
            for (int r = 0; r < 4; r++) sc[i][r] = 0.f;

#pragma unroll
        for (int ks = 0; ks < 8; ks++) {
            const uint32_t qoff = (uint32_t)(wq * 16) * ARS + frag_row + ks * 32 + frag_col;
            uint32_t qh[4], ql[4];
            ldm_x4(qh[0], qh[1], qh[2], qh[3], sb + A_SQH + qoff);
            ldm_x4(ql[0], ql[1], ql[2], ql[3], sb + A_SQL + qoff);
#pragma unroll
            for (int np = 0; np < 4; np++) {
                const uint32_t koff = (uint32_t)(np * 16) * ARS + frag_row + ks * 32 + frag_col;
                uint32_t kh[4], kl[4];
                ldm_x4(kh[0], kh[1], kh[2], kh[3], skv + 0 * AKT + koff);
                ldm_x4(kl[0], kl[1], kl[2], kl[3], skv + 1 * AKT + koff);
                uint32_t bh0[2] = {kh[0], kh[2]}, bh1[2] = {kh[1], kh[3]};
                uint32_t bl0[2] = {kl[0], kl[2]}, bl1[2] = {kl[1], kl[3]};
                mma16816(sc[2 * np],     qh, bh0);
                mma16816(sc[2 * np],     qh, bl0);
                mma16816(sc[2 * np],     ql, bh0);
                mma16816(sc[2 * np + 1], qh, bh1);
                mma16816(sc[2 * np + 1], qh, bl1);
                mma16816(sc[2 * np + 1], ql, bh1);
            }
        }

        const int rg0 = q0 + wq * 16 + (lane >> 2);
        const int rg1 = rg0 + 8;
        const bool diag = (kb >= 2 * qb);
        float mx0 = -INFINITY, mx1 = -INFINITY;
#pragma unroll
        for (int nf = 0; nf < 8; nf++) {
            float t0 = sc[nf][0] * SCL, t1 = sc[nf][1] * SCL;
            float t2 = sc[nf][2] * SCL, t3 = sc[nf][3] * SCL;
            if (diag) {
                const int col = kb * 64 + nf * 8 + (lane & 3) * 2;
                if (col     > rg0) t0 = -INFINITY;
                if (col + 1 > rg0) t1 = -INFINITY;
                if (col     > rg1) t2 = -INFINITY;
                if (col + 1 > rg1) t3 = -INFINITY;
            }
            sc[nf][0] = t0; sc[nf][1] = t1; sc[nf][2] = t2; sc[nf][3] = t3;
            mx0 = fmaxf(mx0, fmaxf(t0, t1));
            mx1 = fmaxf(mx1, fmaxf(t2, t3));
        }
        mx0 = fmaxf(mx0, __shfl_xor_sync(0xffffffffu, mx0, 1));
        mx0 = fmaxf(mx0, __shfl_xor_sync(0xffffffffu, mx0, 2));
        mx1 = fmaxf(mx1, __shfl_xor_sync(0xffffffffu, mx1, 1));
        mx1 = fmaxf(mx1, __shfl_xor_sync(0xffffffffu, mx1, 2));
        const float mn0 = fmaxf(m0, mx0), mn1 = fmaxf(m1, mx1);
        const float corr0 = exp2f(m0 - mn0), corr1 = exp2f(m1 - mn1);
        m0 = mn0; m1 = mn1;

        float rs0 = 0.f, rs1 = 0.f;
#pragma unroll
        for (int nf = 0; nf < 8; nf++) {
            float p0 = exp2f(sc[nf][0] - mn0);
            float p1 = exp2f(sc[nf][1] - mn0);
            float p2 = exp2f(sc[nf][2] - mn1);
            float p3 = exp2f(sc[nf][3] - mn1);
            sc[nf][0] = p0; sc[nf][1] = p1; sc[nf][2] = p2; sc[nf][3] = p3;
            rs0 += p0 + p1; rs1 += p2 + p3;
        }
        rs0 += __shfl_xor_sync(0xffffffffu, rs0, 1);
        rs0 += __shfl_xor_sync(0xffffffffu, rs0, 2);
        rs1 += __shfl_xor_sync(0xffffffffu, rs1, 1);
        rs1 += __shfl_xor_sync(0xffffffffu, rs1, 2);
        l0 = l0 * corr0 + rs0;
        l1 = l1 * corr1 + rs1;
#pragma unroll
        for (int i = 0; i < 16; i++) {
            o[i][0] *= corr0; o[i][1] *= corr0;
            o[i][2] *= corr1; o[i][3] *= corr1;
        }

        uint32_t pAh[4][4], pAl[4][4];
#pragma unroll
        for (int kg = 0; kg < 4; kg++) {
            const float c0 = sc[2 * kg][0], c1 = sc[2 * kg][1];
            const float c2 = sc[2 * kg][2], c3 = sc[2 * kg][3];
            const float d0 = sc[2 * kg + 1][0], d1 = sc[2 * kg + 1][1];
            const float d2 = sc[2 * kg + 1][2], d3 = sc[2 * kg + 1][3];
            pAh[kg][0] = packbf(c0, c1);
            pAh[kg][1] = packbf(c2, c3);
            pAh[kg][2] = packbf(d0, d1);
            pAh[kg][3] = packbf(d2, d3);
            pAl[kg][0] = packbf(c0 - __bfloat162float(__float2bfloat16(c0)),
                                c1 - __bfloat162float(__float2bfloat16(c1)));
            pAl[kg][1] = packbf(c2 - __bfloat162float(__float2bfloat16(c2)),
                                c3 - __bfloat162float(__float2bfloat16(c3)));
            pAl[kg][2] = packbf(d0 - __bfloat162float(__float2bfloat16(d0)),
                                d1 - __bfloat162float(__float2bfloat16(d1)));
            pAl[kg][3] = packbf(d2 - __bfloat162float(__float2bfloat16(d2)),
                                d3 - __bfloat162float(__float2bfloat16(d3)));
        }

#pragma unroll
        for (int dg = 0; dg < 8; dg++) {
#pragma unroll
            for (int kg = 0; kg < 4; kg++) {
                const uint32_t voff = (uint32_t)(kg * 16) * ARS + frag_row + dg * 32 + frag_col;
                uint32_t vh[4], vl[4];
                ldm_x4_t(vh[0], vh[1], vh[2], vh[3], skv + 2 * AKT + voff);
                ldm_x4_t(vl[0], vl[1], vl[2], vl[3], skv + 3 * AKT + voff);
                uint32_t bh0[2] = {vh[0], vh[1]}, bh1[2] = {vh[2], vh[3]};
                uint32_t bl0[2] = {vl[0], vl[1]}, bl1[2] = {vl[2], vl[3]};
                mma16816(o[2 * dg],     pAh[kg], bh0);
                mma16816(o[2 * dg],     pAh[kg], bl0);
                mma16816(o[2 * dg],     pAl[kg], bh0);
                mma16816(o[2 * dg + 1], pAh[kg], bh1);
                mma16816(o[2 * dg + 1], pAh[kg], bl1);
                mma16816(o[2 * dg + 1], pAl[kg], bh1);
            }
        }
    }

    const float inv0 = 1.f / l0, inv1 = 1.f / l1;
    const int rg0 = q0 + wq * 16 + (lane >> 2);
#pragma unroll
    for (int nf = 0; nf < 16; nf++) {
        const int col = h * DH + nf * 8 + (lane & 3) * 2;
        const float a0 = o[nf][0] * inv0, a1 = o[nf][1] * inv0;
        const float a2 = o[nf][2] * inv1, a3 = o[nf][3] * inv1;
        const __nv_bfloat16 h0 = __float2bfloat16(a0), h1 = __float2bfloat16(a1);
        const __nv_bfloat16 h2 = __float2bfloat16(a2), h3 = __float2bfloat16(a3);
        const size_t b0 = (size_t)rg0 * DM + col;
        const size_t b1 = (size_t)(rg0 + 8) * DM + col;
        *(__nv_bfloat162*)(g_zh + b0) = __nv_bfloat162(h0, h1);
        *(__nv_bfloat162*)(g_zh + b1) = __nv_bfloat162(h2, h3);
        *(__nv_bfloat162*)(g_zl + b0) =
            __nv_bfloat162(__float2bfloat16(a0 - __bfloat162float(h0)),
                           __float2bfloat16(a1 - __bfloat162float(h1)));
        *(__nv_bfloat162*)(g_zl + b1) =
            __nv_bfloat162(__float2bfloat16(a2 - __bfloat162float(h2)),
                           __float2bfloat16(a3 - __bfloat162float(h3)));
    }
}

// ---------------------------------------------------------------------------
extern "C" void kernel_launch(void* const* d_in, const int* in_sizes, int n_in,
                              void* d_out, int out_size)
{
    const float* Xq = (const float*)d_in[0];
    const float* Xk = (const float*)d_in[1];
    const float* Xv = (const float*)d_in[2];
    const float* WQ = (const float*)d_in[3];
    const float* bQ = (const float*)d_in[4];
    const float* WK = (const float*)d_in[5];
    const float* bK = (const float*)d_in[6];
    const float* WV = (const float*)d_in[7];
    const float* bV = (const float*)d_in[8];
    const float* WO = (const float*)d_in[9];
    const float* bO = (const float*)d_in[10];
    float* out = (float*)d_out;

    cudaFuncSetAttribute(proj_kernel,
                         cudaFuncAttributeMaxDynamicSharedMemorySize, GEMM_SMEM);
    cudaFuncSetAttribute(wo_gemm_kernel,
                         cudaFuncAttributeMaxDynamicSharedMemorySize, GEMM_SMEM);
    cudaFuncSetAttribute(attn_mma_kernel,
                         cudaFuncAttributeMaxDynamicSharedMemorySize, ATTN_SMEM);

    prepass_kernel<<<PRE_TOTAL, 256>>>(Xq, Xk, Xv, WQ, WK, WV, WO);

    proj_kernel<<<dim3(16, 1, 24), 256, GEMM_SMEM>>>(bQ, bK, bV);

    attn_mma_kernel<<<256, 256, ATTN_SMEM>>>();

    wo_gemm_kernel<<<dim3(16, 16, 1), 256, GEMM_SMEM>>>(out, bO);
}